// round 13
// baseline (speedup 1.0000x reference)
#include <cuda_runtime.h>
#include <cstdint>

// PairwiseDistance: out[b,i,j] = ||x_i||^2 + ||y_j||^2 - 2*<x_i,y_j>
// mma.sync tf32, raw fp32 operands (HW truncation). B fragments REGISTER-
// RESIDENT for all K (64 regs): zero B smem traffic in the mainloop.
// CTA = 128x64 stripe, persists over 4 i-tiles; x-tiles cp.async-prefetched.
// B=2, n=2048, d=64.

#define BATCH 2
#define NROWS 2048
#define DDIM  64

#define BM 128       // i-tile rows
#define BN 64        // CTA j-width
#define IT 4         // i-tiles per CTA
#define SK 68        // smem row stride in floats (64 + 4 pad)

#define XBUF_BYTES (BM * SK * 4)               // 34816
#define SMEM_X0 0
#define SMEM_X1 XBUF_BYTES
#define SMEM_Y  (2 * XBUF_BYTES)               // 69632
#define SMEM_XN (SMEM_Y + BN * SK * 4)         // 87040
#define SMEM_YN (SMEM_XN + BM * 4)             // 87552
#define SMEM_TOTAL (SMEM_YN + BN * 4)          // 87808 B

__device__ __forceinline__ uint32_t smem_u32(const void* p) {
    uint32_t a;
    asm("{ .reg .u64 t; cvta.to.shared.u64 t, %1; cvt.u32.u64 %0, t; }"
        : "=r"(a) : "l"(p));
    return a;
}

__global__ void __launch_bounds__(256, 2)
pdist_kernel(const float* __restrict__ x,
             const float* __restrict__ y,
             float* __restrict__ out) {
    extern __shared__ char smem[];
    float* xn_s = (float*)(smem + SMEM_XN);
    float* yn_s = (float*)(smem + SMEM_YN);

    const int b  = blockIdx.z;
    const int j0 = blockIdx.x * BN;
    const int ig = blockIdx.y;                 // i-tile group: rows ig*IT*BM ...
    const int tid = threadIdx.x;

    const float* xb = x + (size_t)b * NROWS * DDIM;
    const float* yb = y + (size_t)b * NROWS * DDIM;

    const int warp = tid >> 5;
    const int lane = tid & 31;
    const int wrow = warp >> 1;        // 0..3  (32 rows each)
    const int wcol = warp & 1;         // 0..1  (32 cols each)
    const int g    = lane >> 2;        // 0..7
    const int tig  = lane & 3;         // 0..3

    const uint32_t smem_base = smem_u32(smem);
    const uint32_t xs_a[2] = { smem_base + SMEM_X0, smem_base + SMEM_X1 };
    const uint32_t ys_a = smem_base + SMEM_Y;

    // ---- prefetch x-tile 0 via cp.async (8 x 16B per thread) ----
    {
        int i0 = (ig * IT) * BM;
#pragma unroll
        for (int i = 0; i < 8; i++) {
            int e = tid + i * 256;
            int r = e >> 4;
            int c = e & 15;
            uint32_t dst = xs_a[0] + ((r * SK + c * 4) << 2);
            const float* src = xb + (size_t)(i0 + r) * DDIM + c * 4;
            asm volatile("cp.async.cg.shared.global [%0], [%1], 16;"
                         :: "r"(dst), "l"(src));
        }
        asm volatile("cp.async.commit_group;");
    }

    // ---- y prologue: LDG float4, exact norms via 16-lane shuffle, STS ----
    uint32_t* ys = (uint32_t*)(smem + SMEM_Y);
#pragma unroll
    for (int i = 0; i < 4; i++) {
        int e = tid + i * 256;
        int r = e >> 4;                // 0..63
        int c = e & 15;
        float4 vy = *(const float4*)(yb + (size_t)(j0 + r) * DDIM + c * 4);
        float sy = vy.x * vy.x + vy.y * vy.y + vy.z * vy.z + vy.w * vy.w;
#pragma unroll
        for (int m = 1; m < 16; m <<= 1)
            sy += __shfl_xor_sync(0xFFFFFFFFu, sy, m);
        if (c == 0) yn_s[r] = sy;
        *(float4*)(ys + r * SK + c * 4) = vy;
    }
    __syncthreads();

    // ---- load ALL B fragments into registers (verified ldmatrix mapping) ----
    // lane l -> row wcol*32 + (l&7) + (l>>4)*8, koff ((l>>3)&1)*4
    uint32_t bf[8][8];
    {
        uint32_t b_addr = ys_a + (((wcol * 32 + (lane & 7) + (lane >> 4) * 8) * SK +
                                   ((lane >> 3) & 1) * 4) << 2);
#pragma unroll
        for (int ks = 0; ks < 8; ks++) {
#pragma unroll
            for (int p = 0; p < 2; p++) {
                uint32_t bd = b_addr + p * (16 * SK * 4) + ks * 32;
                asm volatile(
                    "ldmatrix.sync.aligned.m8n8.x4.shared.b16 {%0,%1,%2,%3}, [%4];"
                    : "=r"(bf[ks][4 * p + 0]), "=r"(bf[ks][4 * p + 1]),
                      "=r"(bf[ks][4 * p + 2]), "=r"(bf[ks][4 * p + 3])
                    : "r"(bd));
            }
        }
    }

    // ---- i-tile loop ----
    for (int it = 0; it < IT; it++) {
        const int sel = it & 1;
        asm volatile("cp.async.wait_group 0;");
        __syncthreads();                       // bar A: x-tile `it` visible

        // prefetch next x-tile into the other buffer
        if (it + 1 < IT) {
            int i0n = (ig * IT + it + 1) * BM;
#pragma unroll
            for (int i = 0; i < 8; i++) {
                int e = tid + i * 256;
                int r = e >> 4;
                int c = e & 15;
                uint32_t dst = xs_a[sel ^ 1] + ((r * SK + c * 4) << 2);
                const float* src = xb + (size_t)(i0n + r) * DDIM + c * 4;
                asm volatile("cp.async.cg.shared.global [%0], [%1], 16;"
                             :: "r"(dst), "l"(src));
            }
            asm volatile("cp.async.commit_group;");
        }

        // x norms from staged smem (coalesced row chunks + 16-lane shuffle)
        {
            const uint32_t* xs = (const uint32_t*)(smem + (sel ? SMEM_X1 : SMEM_X0));
#pragma unroll
            for (int p = 0; p < 8; p++) {
                int r = (tid >> 4) + p * 16;
                int c = tid & 15;
                float4 v = *(const float4*)(xs + r * SK + c * 4);
                float s = v.x * v.x + v.y * v.y + v.z * v.z + v.w * v.w;
#pragma unroll
                for (int m = 1; m < 16; m <<= 1)
                    s += __shfl_xor_sync(0xFFFFFFFFu, s, m);
                if (c == 0) xn_s[r] = s;
            }
        }
        __syncthreads();                       // bar B: norms ready

        float acc[2][4][4];
#pragma unroll
        for (int fm = 0; fm < 2; fm++)
#pragma unroll
            for (int fn = 0; fn < 4; fn++)
#pragma unroll
                for (int cc = 0; cc < 4; cc++) acc[fm][fn][cc] = 0.f;

        // mainloop: 2 LDSM + 8 MMA per kstep (B from registers)
        uint32_t a_addr = xs_a[sel] +
            (((wrow * 32 + (lane & 15)) * SK + (lane >> 4) * 4) << 2);
#pragma unroll
        for (int ks = 0; ks < 8; ks++) {
            uint32_t a[2][4];
#pragma unroll
            for (int fm = 0; fm < 2; fm++) {
                uint32_t ad = a_addr + fm * (16 * SK * 4) + ks * 32;
                asm volatile(
                    "ldmatrix.sync.aligned.m8n8.x4.shared.b16 {%0,%1,%2,%3}, [%4];"
                    : "=r"(a[fm][0]), "=r"(a[fm][1]),
                      "=r"(a[fm][2]), "=r"(a[fm][3])
                    : "r"(ad));
            }
#pragma unroll
            for (int fm = 0; fm < 2; fm++)
#pragma unroll
                for (int fn = 0; fn < 4; fn++)
                    asm volatile(
                        "mma.sync.aligned.m16n8k8.row.col.f32.tf32.tf32.f32 "
                        "{%0,%1,%2,%3}, {%4,%5,%6,%7}, {%8,%9}, {%0,%1,%2,%3};"
                        : "+f"(acc[fm][fn][0]), "+f"(acc[fm][fn][1]),
                          "+f"(acc[fm][fn][2]), "+f"(acc[fm][fn][3])
                        : "r"(a[fm][0]), "r"(a[fm][1]),
                          "r"(a[fm][2]), "r"(a[fm][3]),
                          "r"(bf[ks][2 * fn]), "r"(bf[ks][2 * fn + 1]));
        }

        // epilogue: out = xnorm + ynorm - 2*dot
        const int i0 = (ig * IT + it) * BM;
        float* outb = out + (size_t)b * NROWS * NROWS;
#pragma unroll
        for (int fm = 0; fm < 2; fm++) {
            int rl = wrow * 32 + fm * 16 + g;
            int r0 = i0 + rl;
            float xn0 = xn_s[rl];
            float xn1 = xn_s[rl + 8];
#pragma unroll
            for (int fn = 0; fn < 4; fn++) {
                int cl = wcol * 32 + fn * 8 + 2 * tig;
                int c = j0 + cl;
                float yn0 = yn_s[cl];
                float yn1 = yn_s[cl + 1];
                float2 v0, v1;
                v0.x = xn0 + yn0 - 2.f * acc[fm][fn][0];
                v0.y = xn0 + yn1 - 2.f * acc[fm][fn][1];
                v1.x = xn1 + yn0 - 2.f * acc[fm][fn][2];
                v1.y = xn1 + yn1 - 2.f * acc[fm][fn][3];
                *(float2*)(outb + (size_t)r0 * NROWS + c)       = v0;
                *(float2*)(outb + (size_t)(r0 + 8) * NROWS + c) = v1;
            }
        }
    }
}

// ---------------------------------------------------------------------------
extern "C" void kernel_launch(void* const* d_in, const int* in_sizes, int n_in,
                              void* d_out, int out_size) {
    const float* x = (const float*)d_in[0];
    const float* y = (const float*)d_in[1];
    float* out = (float*)d_out;

    cudaFuncSetAttribute(pdist_kernel,
                         cudaFuncAttributeMaxDynamicSharedMemorySize,
                         SMEM_TOTAL);

    dim3 grid(NROWS / BN, NROWS / (BM * IT), BATCH);   // 32 x 4 x 2
    pdist_kernel<<<grid, 256, SMEM_TOTAL>>>(x, y, out);
}

// round 14
// speedup vs baseline: 1.1471x; 1.1471x over previous
#include <cuda_runtime.h>
#include <cstdint>

// PairwiseDistance: out[b,i,j] = ||x_i||^2 + ||y_j||^2 - 2*<x_i,y_j>
// mma.sync tf32, raw fp32 operands (HW truncation). ldmatrix fragments.
// 512-thread CTA, tile 128x128, warp tile 32x32 -> 64 regs -> 32 warps/SM
// (8 per SMSP) to cover LDSM->MMA latency.  B=2, n=2048, d=64.

#define BATCH 2
#define NROWS 2048
#define DDIM  64

#define BM 128
#define BN 128
#define SK 68        // smem row stride in floats (64 + 4 pad)

#define SMEM_X  0
#define SMEM_Y  (BM * SK * 4)
#define SMEM_XN (2 * BM * SK * 4)
#define SMEM_YN (SMEM_XN + 512)
#define SMEM_TOTAL (SMEM_YN + 512)         // 70656 B

__device__ __forceinline__ uint32_t smem_u32(const void* p) {
    uint32_t a;
    asm("{ .reg .u64 t; cvta.to.shared.u64 t, %1; cvt.u32.u64 %0, t; }"
        : "=r"(a) : "l"(p));
    return a;
}

__global__ void __launch_bounds__(512, 2)
pdist_kernel(const float* __restrict__ x,
             const float* __restrict__ y,
             float* __restrict__ out) {
    extern __shared__ char smem[];
    uint32_t* xs = (uint32_t*)(smem + SMEM_X);
    uint32_t* ys = (uint32_t*)(smem + SMEM_Y);
    float* xn_s  = (float*)(smem + SMEM_XN);
    float* yn_s  = (float*)(smem + SMEM_YN);

    const int b  = blockIdx.z;
    const int i0 = blockIdx.y * BM;
    const int j0 = blockIdx.x * BN;
    const int tid = threadIdx.x;

    const float* xb = x + (size_t)b * NROWS * DDIM;
    const float* yb = y + (size_t)b * NROWS * DDIM;

    const int warp = tid >> 5;
    const int lane = tid & 31;
    const int wr = warp >> 2;          // 0..3  (32 rows each)
    const int wc = warp & 3;           // 0..3  (32 cols each)
    const int g   = lane >> 2;         // 0..7
    const int tig = lane & 3;          // 0..3

    // ---- prologue: LDG float4, exact-fp32 norms via 16-lane shuffle, STS ----
    // thread -> (row r = e>>4, chunk c = e&15); 16 consecutive tids = one row.
#pragma unroll
    for (int i = 0; i < 4; i++) {
        int e = tid + i * 512;
        int r = e >> 4;
        int c = e & 15;
        float4 vx = *(const float4*)(xb + (size_t)(i0 + r) * DDIM + c * 4);
        float4 vy = *(const float4*)(yb + (size_t)(j0 + r) * DDIM + c * 4);

        float sx = vx.x * vx.x + vx.y * vx.y + vx.z * vx.z + vx.w * vx.w;
        float sy = vy.x * vy.x + vy.y * vy.y + vy.z * vy.z + vy.w * vy.w;
#pragma unroll
        for (int m = 1; m < 16; m <<= 1) {
            sx += __shfl_xor_sync(0xFFFFFFFFu, sx, m);
            sy += __shfl_xor_sync(0xFFFFFFFFu, sy, m);
        }
        if (c == 0) { xn_s[r] = sx; yn_s[r] = sy; }

        *(float4*)(xs + r * SK + c * 4) = vx;   // raw fp32 bits
        *(float4*)(ys + r * SK + c * 4) = vy;
    }
    __syncthreads();

    float acc[2][4][4];
#pragma unroll
    for (int fm = 0; fm < 2; fm++)
#pragma unroll
        for (int fn = 0; fn < 4; fn++)
#pragma unroll
            for (int cc = 0; cc < 4; cc++) acc[fm][fn][cc] = 0.f;

    // ---- ldmatrix base addresses (verified mapping) ----
    // A x4 per fm: lane l -> row wr*32 + fm*16 + (l&15), koff (l>>4)*4
    // B x4 per p (fn=2p,2p+1): lane l -> row wc*32 + p*16 + (l&7)+(l>>4)*8,
    //                          koff ((l>>3)&1)*4
    const uint32_t xs_a = smem_u32(xs);
    const uint32_t ys_a = smem_u32(ys);
    uint32_t a_addr = xs_a + (((wr * 32 + (lane & 15)) * SK + (lane >> 4) * 4) << 2);
    uint32_t b_addr = ys_a + (((wc * 32 + (lane & 7) + (lane >> 4) * 8) * SK +
                               ((lane >> 3) & 1) * 4) << 2);

    // ---- mainloop: 4 LDSM + 8 MMA per kstep, no barriers ----
#pragma unroll
    for (int ks = 0; ks < 8; ks++) {
        uint32_t a[2][4], bb[4][2];
#pragma unroll
        for (int fm = 0; fm < 2; fm++) {
            uint32_t ad = a_addr + fm * (16 * SK * 4) + ks * 32;
            asm volatile(
                "ldmatrix.sync.aligned.m8n8.x4.shared.b16 {%0,%1,%2,%3}, [%4];"
                : "=r"(a[fm][0]), "=r"(a[fm][1]), "=r"(a[fm][2]), "=r"(a[fm][3])
                : "r"(ad));
        }
#pragma unroll
        for (int p = 0; p < 2; p++) {
            uint32_t bd = b_addr + p * (16 * SK * 4) + ks * 32;
            asm volatile(
                "ldmatrix.sync.aligned.m8n8.x4.shared.b16 {%0,%1,%2,%3}, [%4];"
                : "=r"(bb[2 * p][0]), "=r"(bb[2 * p][1]),
                  "=r"(bb[2 * p + 1][0]), "=r"(bb[2 * p + 1][1])
                : "r"(bd));
        }
#pragma unroll
        for (int fm = 0; fm < 2; fm++)
#pragma unroll
            for (int fn = 0; fn < 4; fn++)
                asm volatile(
                    "mma.sync.aligned.m16n8k8.row.col.f32.tf32.tf32.f32 "
                    "{%0,%1,%2,%3}, {%4,%5,%6,%7}, {%8,%9}, {%0,%1,%2,%3};"
                    : "+f"(acc[fm][fn][0]), "+f"(acc[fm][fn][1]),
                      "+f"(acc[fm][fn][2]), "+f"(acc[fm][fn][3])
                    : "r"(a[fm][0]), "r"(a[fm][1]),
                      "r"(a[fm][2]), "r"(a[fm][3]),
                      "r"(bb[fn][0]), "r"(bb[fn][1]));
    }

    // ---- epilogue: out = xnorm + ynorm - 2*dot ----
    float* outb = out + (size_t)b * NROWS * NROWS;

#pragma unroll
    for (int fm = 0; fm < 2; fm++) {
        int rl = wr * 32 + fm * 16 + g;
        int r0 = i0 + rl;
        float xn0 = xn_s[rl];
        float xn1 = xn_s[rl + 8];
#pragma unroll
        for (int fn = 0; fn < 4; fn++) {
            int cl = wc * 32 + fn * 8 + 2 * tig;
            int c = j0 + cl;
            float yn0 = yn_s[cl];
            float yn1 = yn_s[cl + 1];
            float2 v0, v1;
            v0.x = xn0 + yn0 - 2.f * acc[fm][fn][0];
            v0.y = xn0 + yn1 - 2.f * acc[fm][fn][1];
            v1.x = xn1 + yn0 - 2.f * acc[fm][fn][2];
            v1.y = xn1 + yn1 - 2.f * acc[fm][fn][3];
            *(float2*)(outb + (size_t)r0 * NROWS + c)       = v0;
            *(float2*)(outb + (size_t)(r0 + 8) * NROWS + c) = v1;
        }
    }
}

// ---------------------------------------------------------------------------
extern "C" void kernel_launch(void* const* d_in, const int* in_sizes, int n_in,
                              void* d_out, int out_size) {
    const float* x = (const float*)d_in[0];
    const float* y = (const float*)d_in[1];
    float* out = (float*)d_out;

    cudaFuncSetAttribute(pdist_kernel,
                         cudaFuncAttributeMaxDynamicSharedMemorySize,
                         SMEM_TOTAL);

    dim3 grid(NROWS / BN, NROWS / BM, BATCH);   // 16 x 16 x 2
    pdist_kernel<<<grid, 512, SMEM_TOTAL>>>(x, y, out);
}